// round 10
// baseline (speedup 1.0000x reference)
#include <cuda_runtime.h>
#include <math.h>
#include <stdint.h>

#define D 512
#define C 17
#define RMAX 131072
#define NBA 4096
#define NLOW 2048
#define SELCAND 3072
#define LCAP 4096
#define CH2 64

// ---------------- device scratch (static; zero-init at module load) -------
__device__ uint2    g_keys[RMAX];        // {entropy bits, class}
__device__ unsigned g_histA[C * NBA];    // re-zeroed inside k_select
__device__ int      g_cnt[C];
__device__ int      g_list[(size_t)C * LCAP];
__device__ float    g_Wc[C * D];         // zeroed in k_select, REDG in k_sum
__device__ float    g_rn[C];
__device__ unsigned g_done;              // reset by k_sum last block

// ---- kernel 1: bank keys + new-row logits/entropy/argmax, hist pass A ----
__global__ void k_logits(const float* __restrict__ feat,
                         const float* __restrict__ w,
                         const float* __restrict__ bias,
                         const float* __restrict__ entbank,
                         const int*   __restrict__ labels,
                         int B, int N) {
    int tid = blockIdx.x * blockDim.x + threadIdx.x;
    int nth = gridDim.x * blockDim.x;
    for (int i = tid; i < N; i += nth) {
        unsigned bits = __float_as_uint(entbank[i]);  // entropies >= 0: monotone
        int c = labels[i];
        g_keys[i] = make_uint2(bits, (unsigned)c);
        atomicAdd(&g_histA[c * NBA + (bits >> 20)], 1u);
    }

    int warp = tid >> 5;
    int lane = threadIdx.x & 31;
    if (warp >= B) return;

    const float4* f4 = (const float4*)(feat + (size_t)warp * D);
    const float4* w4 = (const float4*)w;
    float4 fv[4];
#pragma unroll
    for (int j = 0; j < 4; j++) fv[j] = f4[lane + 32 * j];

    float s[C];
#pragma unroll
    for (int c = 0; c < C; c++) s[c] = 0.f;
#pragma unroll
    for (int j = 0; j < 4; j++) {
        float4 fj = fv[j];
#pragma unroll
        for (int c = 0; c < C; c++) {
            float4 wv = __ldg(&w4[c * (D / 4) + lane + 32 * j]);
            s[c] += fj.x * wv.x + fj.y * wv.y + fj.z * wv.z + fj.w * wv.w;
        }
    }
#pragma unroll
    for (int o = 16; o; o >>= 1) {
#pragma unroll
        for (int c = 0; c < C; c++)
            s[c] += __shfl_xor_sync(0xffffffffu, s[c], o);
    }
    float pc = -INFINITY;
#pragma unroll
    for (int c = 0; c < C; c++)
        if (lane == c) pc = s[c] + bias[c];

    float m = pc;
#pragma unroll
    for (int o = 16; o; o >>= 1) m = fmaxf(m, __shfl_xor_sync(0xffffffffu, m, o));

    float ex = (lane < C) ? expf(pc - m) : 0.f;
    float tt = (lane < C) ? ex * (pc - m) : 0.f;
    float S = ex, T = tt;
#pragma unroll
    for (int o = 16; o; o >>= 1) {
        S += __shfl_xor_sync(0xffffffffu, S, o);
        T += __shfl_xor_sync(0xffffffffu, T, o);
    }
    float ent = logf(S) - T / S;
    unsigned bal = __ballot_sync(0xffffffffu, (lane < C) && (pc == m));
    int amax = __ffs(bal) - 1;
    if (lane == 0) {
        unsigned bits = __float_as_uint(ent);
        g_keys[N + warp] = make_uint2(bits, (unsigned)amax);
        atomicAdd(&g_histA[amax * NBA + (bits >> 20)], 1u);
    }
}

// ---- kernel 2: per-class full selection (one block per class) ------------
__global__ void __launch_bounds__(256) k_select(const int* __restrict__ kptr, int R) {
    int c = blockIdx.x;
    int t = threadIdx.x;  // 256

    __shared__ unsigned chunk[256];
    __shared__ unsigned incl[256];
    __shared__ unsigned sh_pref;
    __shared__ int sh_kleft;
    __shared__ int s_cnt, s_ccnt;
    __shared__ int sh_thrbin, sh_kl2;
    __shared__ unsigned s_low[NLOW];     // 8 KB
    __shared__ unsigned ckey[SELCAND];   // 12 KB
    __shared__ int      cidx[SELCAND];   // 12 KB

    // ---------- phase A: scan class-c histogram (bits >> 20) ----------
    unsigned* h = &g_histA[c * NBA];
    {
        unsigned s = 0;
#pragma unroll
        for (int j = 0; j < 16; j++) s += h[t * 16 + j];
        chunk[t] = s;
        incl[t] = s;
        if (t == 0) { s_cnt = 0; s_ccnt = 0; sh_pref = 0u; sh_kleft = 0; }
        __syncthreads();
#pragma unroll
        for (int off = 1; off < 256; off <<= 1) {
            unsigned v = (t >= off) ? incl[t - off] : 0u;
            __syncthreads();
            incl[t] += v;
            __syncthreads();
        }
        int tot = (int)incl[255];
        int Kf = kptr[0];
        int k = tot < Kf ? tot : Kf;
        if (k > 0) {
            int excl = (int)incl[t] - (int)chunk[t];
            if ((int)incl[t] >= k && excl < k) {
                int run = excl;
                for (int q = 0; q < 16; q++) {
                    unsigned v = h[t * 16 + q];
                    if (run + (int)v >= k) {
                        sh_pref = (unsigned)(t * 16 + q);
                        sh_kleft = k - run;
                        break;
                    }
                    run += (int)v;
                }
            }
        }
        // CRITICAL: re-walk above reads h; zeroing below writes h. Order them.
        __syncthreads();
        // restore invariants: zero class-c histogram + weight accumulator
        for (int i = t; i < NBA; i += 256) h[i] = 0u;
        for (int d = t; d < D; d += 256) g_Wc[c * D + d] = 0.f;
        for (int i = t; i < NLOW; i += 256) s_low[i] = 0u;
        __syncthreads();
    }
    unsigned pref = sh_pref;
    int kl = sh_kleft;
    bool active = (kl > 0) || (pref > 0u);

    // ---------- phase B: stream keys, filter class c ----------
    int* lst = &g_list[(size_t)c * LCAP];
    if (active) {
        for (int i = t; i < R; i += 256) {
            uint2 kv = __ldg(&g_keys[i]);
            if (kv.y != (unsigned)c) continue;
            unsigned b = kv.x >> 20;
            if (b < pref) {
                int p = atomicAdd(&s_cnt, 1);
                lst[p] = i;
            } else if (b == pref) {
                atomicAdd(&s_low[(kv.x >> 9) & 0x7FFu], 1u);
                int p = atomicAdd(&s_ccnt, 1);
                if (p < SELCAND) { ckey[p] = kv.x; cidx[p] = i; }
            }
        }
    }
    __syncthreads();

    // ---------- phase C: in-smem low-bin scan + tie ranking ----------
    if (active && kl > 0) {
        unsigned s = 0;
#pragma unroll
        for (int j = 0; j < 8; j++) s += s_low[t * 8 + j];
        chunk[t] = s;
        incl[t] = s;
        __syncthreads();
#pragma unroll
        for (int off = 1; off < 256; off <<= 1) {
            unsigned v = (t >= off) ? incl[t - off] : 0u;
            __syncthreads();
            incl[t] += v;
            __syncthreads();
        }
        int excl = (int)incl[t] - (int)chunk[t];
        if ((int)incl[t] >= kl && excl < kl) {
            int run = excl;
            for (int q = 0; q < 8; q++) {
                unsigned v = s_low[t * 8 + q];
                if (run + (int)v >= kl) {
                    sh_thrbin = t * 8 + q;
                    sh_kl2 = kl - run;
                    break;
                }
                run += (int)v;
            }
        }
        __syncthreads();
        int thrbin = sh_thrbin;
        int kl2 = sh_kl2;
        int m = s_ccnt;

        if (m <= SELCAND) {
            for (int j = t; j < m; j += 256) {
                unsigned key = ckey[j];
                int lb = (int)((key >> 9) & 0x7FFu);
                if (lb < thrbin) {
                    int p = atomicAdd(&s_cnt, 1);
                    lst[p] = cidx[j];
                } else if (lb == thrbin) {
                    int idx = cidx[j];
                    int rank = 0;
                    for (int q = 0; q < m; q++) {
                        unsigned kq = ckey[q];
                        if ((int)((kq >> 9) & 0x7FFu) != thrbin) continue;
                        rank += (kq < key) || (kq == key && cidx[q] < idx);
                    }
                    if (rank < kl2) {
                        int p = atomicAdd(&s_cnt, 1);
                        lst[p] = idx;
                    }
                }
            }
        } else {
            // rare fallback: candidate overflow -> re-stream global keys
            unsigned tiepfx = (pref << 11) | (unsigned)thrbin;
            for (int i = t; i < R; i += 256) {
                uint2 kv = __ldg(&g_keys[i]);
                if (kv.y != (unsigned)c) continue;
                unsigned b = kv.x >> 20;
                if (b != pref) continue;
                int lb = (int)((kv.x >> 9) & 0x7FFu);
                if (lb < thrbin) {
                    int p = atomicAdd(&s_cnt, 1);
                    lst[p] = i;
                } else if ((kv.x >> 9) == tiepfx) {
                    unsigned key = kv.x;
                    int rank = 0;
                    for (int q = 0; q < R; q++) {
                        uint2 kq = g_keys[q];
                        if (kq.y != (unsigned)c) continue;
                        if ((kq.x >> 9) != tiepfx) continue;
                        rank += (kq.x < key) || (kq.x == key && q < i);
                    }
                    if (rank < kl2) {
                        int p = atomicAdd(&s_cnt, 1);
                        lst[p] = i;
                    }
                }
            }
        }
    }
    __syncthreads();
    if (t == 0) g_cnt[c] = s_cnt;
}

// ---- kernel 3: support sums -> REDG into g_Wc; last block -> norms -------
__global__ void k_sum(const float* __restrict__ supports,
                      const float* __restrict__ feat, int N) {
    int c = blockIdx.y;
    int blk = blockIdx.x;
    int cnt = g_cnt[c]; if (cnt > LCAP) cnt = LCAP;
    int w = threadIdx.x >> 5, lane = threadIdx.x & 31;
    int wg = blk * 8 + w;
    const int* lst = &g_list[(size_t)c * LCAP];

    float acc[16];
#pragma unroll
    for (int j = 0; j < 16; j++) acc[j] = 0.f;

    for (int idx = wg; idx < cnt; idx += CH2 * 8) {
        int r = lst[idx];
        const float4* p = (const float4*)((r < N) ? supports + (size_t)r * D
                                                  : feat + (size_t)(r - N) * D);
        float4 v[4];
        float ss = 0.f;
#pragma unroll
        for (int j = 0; j < 4; j++) {
            v[j] = p[lane + 32 * j];
            ss += v[j].x * v[j].x + v[j].y * v[j].y + v[j].z * v[j].z + v[j].w * v[j].w;
        }
#pragma unroll
        for (int o = 16; o; o >>= 1) ss += __shfl_xor_sync(0xffffffffu, ss, o);
        float rn = 1.f / fmaxf(sqrtf(ss), 1e-12f);
#pragma unroll
        for (int j = 0; j < 4; j++) {
            acc[4 * j + 0] += v[j].x * rn;
            acc[4 * j + 1] += v[j].y * rn;
            acc[4 * j + 2] += v[j].z * rn;
            acc[4 * j + 3] += v[j].w * rn;
        }
    }

    __shared__ float sacc[D];
    for (int d = threadIdx.x; d < D; d += blockDim.x) sacc[d] = 0.f;
    __syncthreads();
#pragma unroll
    for (int j = 0; j < 4; j++) {
        int d = 4 * (lane + 32 * j);
        atomicAdd(&sacc[d + 0], acc[4 * j + 0]);
        atomicAdd(&sacc[d + 1], acc[4 * j + 1]);
        atomicAdd(&sacc[d + 2], acc[4 * j + 2]);
        atomicAdd(&sacc[d + 3], acc[4 * j + 3]);
    }
    __syncthreads();
    for (int d = threadIdx.x; d < D; d += blockDim.x)
        atomicAdd(&g_Wc[c * D + d], sacc[d]);   // REDG, no return

    // all threads fence their REDGs, then one thread claims the done slot
    __syncthreads();
    __threadfence();
    __syncthreads();
    __shared__ int amlast;
    if (threadIdx.x == 0) {
        unsigned v = atomicAdd(&g_done, 1u);
        amlast = (v == (unsigned)(gridDim.x * gridDim.y - 1));
    }
    __syncthreads();
    if (!amlast) return;
    if (threadIdx.x == 0) g_done = 0u;
    for (int cc = w; cc < C; cc += 8) {
        float ss = 0.f;
#pragma unroll
        for (int j = 0; j < 16; j++) {
            float v = g_Wc[cc * D + lane + 32 * j];
            ss += v * v;
        }
#pragma unroll
        for (int o = 16; o; o >>= 1) ss += __shfl_xor_sync(0xffffffffu, ss, o);
        if (lane == 0)
            g_rn[cc] = 1.f / fmaxf(sqrtf(ss), 1e-12f);
    }
}

// ---- kernel 4: final GEMM out = feature @ (Wc * rn) -----------------------
__global__ void k_gemm2(const float* __restrict__ feat, float* __restrict__ out,
                        int B) {
    int tid = blockIdx.x * blockDim.x + threadIdx.x;
    int warp = tid >> 5;
    int lane = threadIdx.x & 31;
    if (warp >= B) return;
    float rnl = (lane < C) ? g_rn[lane] : 0.f;
    const float4* f4 = (const float4*)(feat + (size_t)warp * D);
    const float4* w4 = (const float4*)g_Wc;
    float4 fv[4];
#pragma unroll
    for (int j = 0; j < 4; j++) fv[j] = f4[lane + 32 * j];
    float s[C];
#pragma unroll
    for (int c = 0; c < C; c++) s[c] = 0.f;
#pragma unroll
    for (int j = 0; j < 4; j++) {
        float4 fj = fv[j];
#pragma unroll
        for (int c = 0; c < C; c++) {
            float4 wv = w4[c * (D / 4) + lane + 32 * j];
            s[c] += fj.x * wv.x + fj.y * wv.y + fj.z * wv.z + fj.w * wv.w;
        }
    }
#pragma unroll
    for (int o = 16; o; o >>= 1) {
#pragma unroll
        for (int c = 0; c < C; c++)
            s[c] += __shfl_xor_sync(0xffffffffu, s[c], o);
    }
    float myv = 0.f;
#pragma unroll
    for (int c = 0; c < C; c++)
        if (lane == c) myv = s[c];
    if (lane < C) out[(size_t)warp * C + lane] = myv * rnl;
}

// ---- launch ---------------------------------------------------------------
extern "C" void kernel_launch(void* const* d_in, const int* in_sizes, int n_in,
                              void* d_out, int out_size) {
    const float* feature  = (const float*)d_in[0];
    const float* clf_w    = (const float*)d_in[1];
    const float* clf_b    = (const float*)d_in[2];
    const float* supports = (const float*)d_in[3];
    const float* ent_bank = (const float*)d_in[4];
    const int*   labels   = (const int*)d_in[5];
    const int*   kptr     = (const int*)d_in[6];

    int Cc = in_sizes[2];          // 17
    int Dv = in_sizes[1] / Cc;     // 512
    int B  = in_sizes[0] / Dv;     // 4096
    int N  = in_sizes[4];          // 100000
    int R  = N + B;
    (void)n_in; (void)out_size; (void)Dv;

    float* out = (float*)d_out;

    int blk1 = (B * 32 + 255) / 256;
    k_logits<<<blk1, 256>>>(feature, clf_w, clf_b, ent_bank, labels, B, N);
    k_select<<<C, 256>>>(kptr, R);
    dim3 g3(CH2, C);
    k_sum<<<g3, 256>>>(supports, feature, N);
    k_gemm2<<<blk1, 256>>>(feature, out, B);
}

// round 11
// speedup vs baseline: 2.4423x; 2.4423x over previous
#include <cuda_runtime.h>
#include <math.h>
#include <stdint.h>

#define D 512
#define C 17
#define RMAX 131072
#define NBA 4096
#define NLOW 2048
#define CANDCAP 32768
#define TIECAP 512
#define LCAP 4096
#define CH2 64

// ---------------- device scratch (static; zero-init at module load) -------
__device__ uint2    g_keys[RMAX];        // {entropy bits, class}
__device__ unsigned g_histA[C * NBA];    // re-zeroed by k_selB each run
__device__ unsigned g_lowhist[C * NLOW]; // re-zeroed by k_selB each run
__device__ unsigned g_prefA[C];
__device__ int      g_kleft[C];
__device__ int      g_cnt[C];
__device__ int      g_candcnt[C];
__device__ int      g_cand[C][CANDCAP];
__device__ int      g_list[(size_t)C * LCAP];
__device__ float    g_part[(size_t)C * CH2 * D];
__device__ float    g_Wcn[C * D];

// ---- kernel 1: bank keys + new-row logits/entropy/argmax, hist pass A ----
__global__ void k_logits(const float* __restrict__ feat,
                         const float* __restrict__ w,
                         const float* __restrict__ bias,
                         const float* __restrict__ entbank,
                         const int*   __restrict__ labels,
                         int B, int N) {
    int tid = blockIdx.x * blockDim.x + threadIdx.x;
    int nth = gridDim.x * blockDim.x;
    for (int i = tid; i < N; i += nth) {
        unsigned bits = __float_as_uint(entbank[i]);  // entropies >= 0: monotone
        int c = labels[i];
        g_keys[i] = make_uint2(bits, (unsigned)c);
        atomicAdd(&g_histA[c * NBA + (bits >> 20)], 1u);
    }

    int warp = tid >> 5;
    int lane = threadIdx.x & 31;
    if (warp >= B) return;

    const float4* f4 = (const float4*)(feat + (size_t)warp * D);
    const float4* w4 = (const float4*)w;
    float4 fv[4];
#pragma unroll
    for (int j = 0; j < 4; j++) fv[j] = f4[lane + 32 * j];

    float s[C];
#pragma unroll
    for (int c = 0; c < C; c++) s[c] = 0.f;
#pragma unroll
    for (int j = 0; j < 4; j++) {
        float4 fj = fv[j];
#pragma unroll
        for (int c = 0; c < C; c++) {
            float4 wv = __ldg(&w4[c * (D / 4) + lane + 32 * j]);
            s[c] += fj.x * wv.x + fj.y * wv.y + fj.z * wv.z + fj.w * wv.w;
        }
    }
#pragma unroll
    for (int o = 16; o; o >>= 1) {
#pragma unroll
        for (int c = 0; c < C; c++)
            s[c] += __shfl_xor_sync(0xffffffffu, s[c], o);
    }
    float pc = -INFINITY;
#pragma unroll
    for (int c = 0; c < C; c++)
        if (lane == c) pc = s[c] + bias[c];

    float m = pc;
#pragma unroll
    for (int o = 16; o; o >>= 1) m = fmaxf(m, __shfl_xor_sync(0xffffffffu, m, o));

    float ex = (lane < C) ? expf(pc - m) : 0.f;
    float tt = (lane < C) ? ex * (pc - m) : 0.f;
    float S = ex, T = tt;
#pragma unroll
    for (int o = 16; o; o >>= 1) {
        S += __shfl_xor_sync(0xffffffffu, S, o);
        T += __shfl_xor_sync(0xffffffffu, T, o);
    }
    float ent = logf(S) - T / S;
    unsigned bal = __ballot_sync(0xffffffffu, (lane < C) && (pc == m));
    int amax = __ffs(bal) - 1;
    if (lane == 0) {
        unsigned bits = __float_as_uint(ent);
        g_keys[N + warp] = make_uint2(bits, (unsigned)amax);
        atomicAdd(&g_histA[amax * NBA + (bits >> 20)], 1u);
    }
}

// ---- kernel 2: scan pass A (parallel prefix) -> 12-bit bin per class -----
__global__ void k_scanA(const int* __restrict__ kptr) {
    int c = blockIdx.x;
    int t = threadIdx.x;  // 256
    const unsigned* h = &g_histA[c * NBA];
    __shared__ unsigned chunk[256];
    __shared__ unsigned incl[256];
    unsigned s = 0;
#pragma unroll
    for (int j = 0; j < 16; j++) s += h[t * 16 + j];
    chunk[t] = s;
    incl[t] = s;
    __syncthreads();
#pragma unroll
    for (int off = 1; off < 256; off <<= 1) {
        unsigned v = (t >= off) ? incl[t - off] : 0u;
        __syncthreads();
        incl[t] += v;
        __syncthreads();
    }
    int tot = (int)incl[255];
    int Kf = kptr[0];
    int k = tot < Kf ? tot : Kf;
    if (t == 0) {
        g_cnt[c] = 0;
        g_candcnt[c] = 0;
        if (k <= 0) { g_prefA[c] = 0u; g_kleft[c] = 0; }
    }
    if (k <= 0) return;
    int excl = (int)incl[t] - (int)chunk[t];
    if ((int)incl[t] >= k && excl < k) {
        int run = excl;
        for (int q = 0; q < 16; q++) {
            unsigned v = h[t * 16 + q];
            if (run + (int)v >= k) {
                g_prefA[c] = (unsigned)(t * 16 + q);
                g_kleft[c] = k - run;
                break;
            }
            run += (int)v;
        }
    }
}

// ---- kernel 3: compact below rows + candidates + low-bit sub-histogram ---
__global__ void k_compact(int R) {
    __shared__ unsigned s_pref[C];
    if (threadIdx.x < C) s_pref[threadIdx.x] = g_prefA[threadIdx.x];
    __syncthreads();
    int tid = blockIdx.x * blockDim.x + threadIdx.x;
    int nth = gridDim.x * blockDim.x;
    for (int i = tid; i < R; i += nth) {
        uint2 kv = __ldg(&g_keys[i]);
        int c = (int)kv.y;
        unsigned bits = kv.x;
        unsigned b = bits >> 20;
        unsigned pa = s_pref[c];
        bool below = (b < pa);
        bool equal = (b == pa);
        unsigned act = __ballot_sync(0xffffffffu, below);
        if (below) {
            unsigned peers = __match_any_sync(act, c);
            int leader = __ffs(peers) - 1;
            int rank = __popc(peers & ((1u << (threadIdx.x & 31)) - 1u));
            int base = 0;
            if ((threadIdx.x & 31) == leader)
                base = atomicAdd(&g_cnt[c], __popc(peers));
            base = __shfl_sync(peers, base, leader);
            g_list[(size_t)c * LCAP + base + rank] = i;
        }
        unsigned act2 = __ballot_sync(0xffffffffu, equal);
        if (equal) {
            unsigned peers = __match_any_sync(act2, c);
            int leader = __ffs(peers) - 1;
            int rank = __popc(peers & ((1u << (threadIdx.x & 31)) - 1u));
            int base = 0;
            if ((threadIdx.x & 31) == leader)
                base = atomicAdd(&g_candcnt[c], __popc(peers));
            base = __shfl_sync(peers, base, leader);
            int p = base + rank;
            if (p < CANDCAP) g_cand[c][p] = i;
            atomicAdd(&g_lowhist[c * NLOW + ((bits >> 9) & 0x7FFu)], 1u);
        }
    }
}

// ---- kernel 4: exact select via low-bin scan + tiny tie ranking ----------
__global__ void k_selB() {
    int c = blockIdx.x;
    int t = threadIdx.x;  // 256
    int k = g_kleft[c];
    int m = g_candcnt[c]; if (m > CANDCAP) m = CANDCAP;
    const int* lst = g_cand[c];
    unsigned* lh = &g_lowhist[c * NLOW];

    __shared__ unsigned chunk[256];
    __shared__ unsigned incl[256];
    __shared__ int sh_thrbin, sh_kl2;
    __shared__ unsigned tkey[TIECAP];
    __shared__ int      tidx[TIECAP];
    __shared__ int      tcnt;

    if (k > 0 && m > 0) {
        unsigned s = 0;
#pragma unroll
        for (int j = 0; j < 8; j++) s += lh[t * 8 + j];
        chunk[t] = s;
        incl[t] = s;
        if (t == 0) tcnt = 0;
        __syncthreads();
#pragma unroll
        for (int off = 1; off < 256; off <<= 1) {
            unsigned v = (t >= off) ? incl[t - off] : 0u;
            __syncthreads();
            incl[t] += v;
            __syncthreads();
        }
        int excl = (int)incl[t] - (int)chunk[t];
        if ((int)incl[t] >= k && excl < k) {
            int run = excl;
            for (int q = 0; q < 8; q++) {
                unsigned v = lh[t * 8 + q];
                if (run + (int)v >= k) {
                    sh_thrbin = t * 8 + q;
                    sh_kl2 = k - run;
                    break;
                }
                run += (int)v;
            }
        }
        __syncthreads();
        int thrbin = sh_thrbin;
        int kl2 = sh_kl2;

        for (int j = t; j < m; j += 256) {
            int idx = lst[j];
            unsigned bits = g_keys[idx].x;
            int lb = (int)((bits >> 9) & 0x7FFu);
            if (lb < thrbin) {
                int p = atomicAdd(&g_cnt[c], 1);
                g_list[(size_t)c * LCAP + p] = idx;
            } else if (lb == thrbin) {
                int p = atomicAdd(&tcnt, 1);
                if (p < TIECAP) { tkey[p] = bits; tidx[p] = idx; }
            }
        }
        __syncthreads();
        int tc = tcnt;
        if (tc <= TIECAP) {
            for (int j = t; j < tc; j += 256) {
                unsigned key = tkey[j];
                int idx = tidx[j];
                int rank = 0;
                for (int q = 0; q < tc; q++) {
                    unsigned kq = tkey[q];
                    rank += (kq < key) || (kq == key && tidx[q] < idx);
                }
                if (rank < kl2) {
                    int p = atomicAdd(&g_cnt[c], 1);
                    g_list[(size_t)c * LCAP + p] = idx;
                }
            }
        } else {
            for (int j = t; j < m; j += 256) {
                int idx = lst[j];
                unsigned key = g_keys[idx].x;
                if ((int)((key >> 9) & 0x7FFu) != thrbin) continue;
                int rank = 0;
                for (int q = 0; q < m; q++) {
                    int iq = lst[q];
                    unsigned kq = g_keys[iq].x;
                    if ((int)((kq >> 9) & 0x7FFu) != thrbin) continue;
                    rank += (kq < key) || (kq == key && iq < idx);
                }
                if (rank < kl2) {
                    int p = atomicAdd(&g_cnt[c], 1);
                    g_list[(size_t)c * LCAP + p] = idx;
                }
            }
        }
    }
    // restore zero invariants for next run
    for (int i = t; i < NBA; i += 256) g_histA[c * NBA + i] = 0u;
    for (int i = t; i < NLOW; i += 256) g_lowhist[c * NLOW + i] = 0u;
}

// ---- kernel 5: normalized per-class support sums (register accumulate) ---
__global__ void k_sum(const float* __restrict__ supports,
                      const float* __restrict__ feat, int N) {
    int c = blockIdx.y;
    int blk = blockIdx.x;
    int cnt = g_cnt[c]; if (cnt > LCAP) cnt = LCAP;
    int w = threadIdx.x >> 5, lane = threadIdx.x & 31;
    int wg = blk * 8 + w;
    const int* lst = &g_list[(size_t)c * LCAP];

    float acc[16];
#pragma unroll
    for (int j = 0; j < 16; j++) acc[j] = 0.f;

    for (int idx = wg; idx < cnt; idx += CH2 * 8) {
        int r = lst[idx];
        const float4* p = (const float4*)((r < N) ? supports + (size_t)r * D
                                                  : feat + (size_t)(r - N) * D);
        float4 v[4];
        float ss = 0.f;
#pragma unroll
        for (int j = 0; j < 4; j++) {
            v[j] = p[lane + 32 * j];
            ss += v[j].x * v[j].x + v[j].y * v[j].y + v[j].z * v[j].z + v[j].w * v[j].w;
        }
#pragma unroll
        for (int o = 16; o; o >>= 1) ss += __shfl_xor_sync(0xffffffffu, ss, o);
        float rn = 1.f / fmaxf(sqrtf(ss), 1e-12f);
#pragma unroll
        for (int j = 0; j < 4; j++) {
            acc[4 * j + 0] += v[j].x * rn;
            acc[4 * j + 1] += v[j].y * rn;
            acc[4 * j + 2] += v[j].z * rn;
            acc[4 * j + 3] += v[j].w * rn;
        }
    }

    __shared__ float sacc[D];
    for (int d = threadIdx.x; d < D; d += blockDim.x) sacc[d] = 0.f;
    __syncthreads();
#pragma unroll
    for (int j = 0; j < 4; j++) {
        int d = 4 * (lane + 32 * j);
        atomicAdd(&sacc[d + 0], acc[4 * j + 0]);
        atomicAdd(&sacc[d + 1], acc[4 * j + 1]);
        atomicAdd(&sacc[d + 2], acc[4 * j + 2]);
        atomicAdd(&sacc[d + 3], acc[4 * j + 3]);
    }
    __syncthreads();
    float* dst = &g_part[((size_t)c * CH2 + blk) * D];
    for (int d = threadIdx.x; d < D; d += blockDim.x) dst[d] = sacc[d];
}

// ---- kernel 6: reduce partials + column-normalize ------------------------
__global__ void k_finalW() {
    int c = blockIdx.x;
    int t = threadIdx.x;  // 256
    float s0 = 0.f, s1 = 0.f;
#pragma unroll 4
    for (int j = 0; j < CH2; j++) {
        const float* p = &g_part[((size_t)c * CH2 + j) * D];
        s0 += p[t];
        s1 += p[t + 256];
    }
    float ss = s0 * s0 + s1 * s1;
    __shared__ float red[8];
#pragma unroll
    for (int o = 16; o; o >>= 1) ss += __shfl_xor_sync(0xffffffffu, ss, o);
    if ((t & 31) == 0) red[t >> 5] = ss;
    __syncthreads();
    float tot;
    {
        float v = (t < 8) ? red[t] : 0.f;
#pragma unroll
        for (int o = 4; o; o >>= 1) v += __shfl_xor_sync(0xffffffffu, v, o);
        __shared__ float sh_tot;
        if (t == 0) sh_tot = v;
        __syncthreads();
        tot = sh_tot;
    }
    float rn = 1.f / fmaxf(sqrtf(tot), 1e-12f);
    g_Wcn[c * D + t] = s0 * rn;
    g_Wcn[c * D + t + 256] = s1 * rn;
}

// ---- kernel 7: final GEMM out = feature @ w_norm (vectorized) ------------
__global__ void k_gemm2(const float* __restrict__ feat, float* __restrict__ out,
                        int B) {
    int tid = blockIdx.x * blockDim.x + threadIdx.x;
    int warp = tid >> 5;
    int lane = threadIdx.x & 31;
    if (warp >= B) return;
    const float4* f4 = (const float4*)(feat + (size_t)warp * D);
    const float4* w4 = (const float4*)g_Wcn;
    float4 fv[4];
#pragma unroll
    for (int j = 0; j < 4; j++) fv[j] = f4[lane + 32 * j];
    float s[C];
#pragma unroll
    for (int c = 0; c < C; c++) s[c] = 0.f;
#pragma unroll
    for (int j = 0; j < 4; j++) {
        float4 fj = fv[j];
#pragma unroll
        for (int c = 0; c < C; c++) {
            float4 wv = w4[c * (D / 4) + lane + 32 * j];
            s[c] += fj.x * wv.x + fj.y * wv.y + fj.z * wv.z + fj.w * wv.w;
        }
    }
#pragma unroll
    for (int o = 16; o; o >>= 1) {
#pragma unroll
        for (int c = 0; c < C; c++)
            s[c] += __shfl_xor_sync(0xffffffffu, s[c], o);
    }
    float myv = 0.f;
#pragma unroll
    for (int c = 0; c < C; c++)
        if (lane == c) myv = s[c];
    if (lane < C) out[(size_t)warp * C + lane] = myv;
}

// ---- launch ---------------------------------------------------------------
extern "C" void kernel_launch(void* const* d_in, const int* in_sizes, int n_in,
                              void* d_out, int out_size) {
    const float* feature  = (const float*)d_in[0];
    const float* clf_w    = (const float*)d_in[1];
    const float* clf_b    = (const float*)d_in[2];
    const float* supports = (const float*)d_in[3];
    const float* ent_bank = (const float*)d_in[4];
    const int*   labels   = (const int*)d_in[5];
    const int*   kptr     = (const int*)d_in[6];

    int Cc = in_sizes[2];          // 17
    int Dv = in_sizes[1] / Cc;     // 512
    int B  = in_sizes[0] / Dv;     // 4096
    int N  = in_sizes[4];          // 100000
    int R  = N + B;
    (void)n_in; (void)out_size; (void)Dv;

    float* out = (float*)d_out;

    int blk1 = (B * 32 + 255) / 256;
    k_logits<<<blk1, 256>>>(feature, clf_w, clf_b, ent_bank, labels, B, N);
    k_scanA<<<C, 256>>>(kptr);
    k_compact<<<(R + 255) / 256, 256>>>(R);
    k_selB<<<C, 256>>>();
    dim3 g5(CH2, C);
    k_sum<<<g5, 256>>>(supports, feature, N);
    k_finalW<<<C, 256>>>();
    k_gemm2<<<blk1, 256>>>(feature, out, B);
}

// round 12
// speedup vs baseline: 2.6140x; 1.0703x over previous
#include <cuda_runtime.h>
#include <math.h>
#include <stdint.h>

#define D 512
#define C 17
#define RMAX 131072
#define NBA 4096
#define NLOW 256
#define CANDCAP 32768
#define TIECAP 512
#define LCAP 4096
#define CH2 64

// ---------------- device scratch (static; zero-init at module load) -------
__device__ uint2    g_keys[RMAX];        // {entropy bits, class}
__device__ unsigned g_histA[C * NBA];    // re-zeroed by k_gemm2 each run
__device__ unsigned g_lowhist[C * NLOW]; // re-zeroed by k_gemm2 each run
__device__ unsigned g_prefA[C];
__device__ int      g_kleft[C];
__device__ int      g_cnt[C];
__device__ int      g_candcnt[C];
__device__ int      g_cand[C][CANDCAP];
__device__ int      g_list[(size_t)C * LCAP];
__device__ float    g_Wc[C * D];         // zeroed in k_scanA, REDG in k_sum
__device__ float    g_rn[C];
__device__ unsigned g_done;              // reset by k_sum last block

// ---- kernel 1: bank keys + new-row logits/entropy/argmax, hist pass A ----
__global__ void k_logits(const float* __restrict__ feat,
                         const float* __restrict__ w,
                         const float* __restrict__ bias,
                         const float* __restrict__ entbank,
                         const int*   __restrict__ labels,
                         int B, int N) {
    int tid = blockIdx.x * blockDim.x + threadIdx.x;
    int nth = gridDim.x * blockDim.x;
    for (int i = tid; i < N; i += nth) {
        unsigned bits = __float_as_uint(entbank[i]);  // entropies >= 0: monotone
        int c = labels[i];
        g_keys[i] = make_uint2(bits, (unsigned)c);
        atomicAdd(&g_histA[c * NBA + (bits >> 20)], 1u);
    }

    int warp = tid >> 5;
    int lane = threadIdx.x & 31;
    if (warp >= B) return;

    const float4* f4 = (const float4*)(feat + (size_t)warp * D);
    const float4* w4 = (const float4*)w;
    float4 fv[4];
#pragma unroll
    for (int j = 0; j < 4; j++) fv[j] = f4[lane + 32 * j];

    float s[C];
#pragma unroll
    for (int c = 0; c < C; c++) s[c] = 0.f;
#pragma unroll
    for (int j = 0; j < 4; j++) {
        float4 fj = fv[j];
#pragma unroll
        for (int c = 0; c < C; c++) {
            float4 wv = __ldg(&w4[c * (D / 4) + lane + 32 * j]);
            s[c] += fj.x * wv.x + fj.y * wv.y + fj.z * wv.z + fj.w * wv.w;
        }
    }
#pragma unroll
    for (int o = 16; o; o >>= 1) {
#pragma unroll
        for (int c = 0; c < C; c++)
            s[c] += __shfl_xor_sync(0xffffffffu, s[c], o);
    }
    float pc = -INFINITY;
#pragma unroll
    for (int c = 0; c < C; c++)
        if (lane == c) pc = s[c] + bias[c];

    float m = pc;
#pragma unroll
    for (int o = 16; o; o >>= 1) m = fmaxf(m, __shfl_xor_sync(0xffffffffu, m, o));

    float ex = (lane < C) ? expf(pc - m) : 0.f;
    float tt = (lane < C) ? ex * (pc - m) : 0.f;
    float S = ex, T = tt;
#pragma unroll
    for (int o = 16; o; o >>= 1) {
        S += __shfl_xor_sync(0xffffffffu, S, o);
        T += __shfl_xor_sync(0xffffffffu, T, o);
    }
    float ent = logf(S) - T / S;
    unsigned bal = __ballot_sync(0xffffffffu, (lane < C) && (pc == m));
    int amax = __ffs(bal) - 1;
    if (lane == 0) {
        unsigned bits = __float_as_uint(ent);
        g_keys[N + warp] = make_uint2(bits, (unsigned)amax);
        atomicAdd(&g_histA[amax * NBA + (bits >> 20)], 1u);
    }
}

// ---- kernel 2: scan pass A -> 12-bit bin per class; zero g_Wc ------------
__global__ void k_scanA(const int* __restrict__ kptr) {
    int c = blockIdx.x;
    int t = threadIdx.x;  // 256
    const unsigned* h = &g_histA[c * NBA];
    __shared__ unsigned chunk[256];
    __shared__ unsigned incl[256];
    unsigned s = 0;
#pragma unroll
    for (int j = 0; j < 16; j++) s += h[t * 16 + j];
    chunk[t] = s;
    incl[t] = s;
    // zero the weight accumulator for k_sum's REDG
    g_Wc[c * D + t] = 0.f;
    g_Wc[c * D + t + 256] = 0.f;
    __syncthreads();
#pragma unroll
    for (int off = 1; off < 256; off <<= 1) {
        unsigned v = (t >= off) ? incl[t - off] : 0u;
        __syncthreads();
        incl[t] += v;
        __syncthreads();
    }
    int tot = (int)incl[255];
    int Kf = kptr[0];
    int k = tot < Kf ? tot : Kf;
    if (t == 0) {
        g_cnt[c] = 0;
        g_candcnt[c] = 0;
        if (k <= 0) { g_prefA[c] = 0u; g_kleft[c] = 0; }
    }
    if (k <= 0) return;
    int excl = (int)incl[t] - (int)chunk[t];
    if ((int)incl[t] >= k && excl < k) {
        int run = excl;
        for (int q = 0; q < 16; q++) {
            unsigned v = h[t * 16 + q];
            if (run + (int)v >= k) {
                g_prefA[c] = (unsigned)(t * 16 + q);
                g_kleft[c] = k - run;
                break;
            }
            run += (int)v;
        }
    }
}

// ---- kernel 3: compact below rows + candidates + 8-bit sub-histogram -----
__global__ void k_compact(int R) {
    __shared__ unsigned s_pref[C];
    if (threadIdx.x < C) s_pref[threadIdx.x] = g_prefA[threadIdx.x];
    __syncthreads();
    int tid = blockIdx.x * blockDim.x + threadIdx.x;
    int nth = gridDim.x * blockDim.x;
    for (int i = tid; i < R; i += nth) {
        uint2 kv = __ldg(&g_keys[i]);
        int c = (int)kv.y;
        unsigned bits = kv.x;
        unsigned b = bits >> 20;
        unsigned pa = s_pref[c];
        bool below = (b < pa);
        bool equal = (b == pa);
        unsigned act = __ballot_sync(0xffffffffu, below);
        if (below) {
            unsigned peers = __match_any_sync(act, c);
            int leader = __ffs(peers) - 1;
            int rank = __popc(peers & ((1u << (threadIdx.x & 31)) - 1u));
            int base = 0;
            if ((threadIdx.x & 31) == leader)
                base = atomicAdd(&g_cnt[c], __popc(peers));
            base = __shfl_sync(peers, base, leader);
            g_list[(size_t)c * LCAP + base + rank] = i;
        }
        unsigned act2 = __ballot_sync(0xffffffffu, equal);
        if (equal) {
            unsigned peers = __match_any_sync(act2, c);
            int leader = __ffs(peers) - 1;
            int rank = __popc(peers & ((1u << (threadIdx.x & 31)) - 1u));
            int base = 0;
            if ((threadIdx.x & 31) == leader)
                base = atomicAdd(&g_candcnt[c], __popc(peers));
            base = __shfl_sync(peers, base, leader);
            int p = base + rank;
            if (p < CANDCAP) g_cand[c][p] = i;
            atomicAdd(&g_lowhist[c * NLOW + ((bits >> 12) & 0xFFu)], 1u);
        }
    }
}

// ---- kernel 4: exact select via 256-bin scan + tiny tie ranking ----------
__global__ void k_selB() {
    int c = blockIdx.x;
    int t = threadIdx.x;  // 256
    int k = g_kleft[c];
    int m = g_candcnt[c]; if (m > CANDCAP) m = CANDCAP;
    const int* lst = g_cand[c];

    __shared__ unsigned chunk[256];
    __shared__ unsigned incl[256];
    __shared__ int sh_thrbin, sh_kl2;
    __shared__ unsigned tkey[TIECAP];
    __shared__ int      tidx[TIECAP];
    __shared__ int      tcnt;

    if (k <= 0 || m <= 0) return;

    unsigned s = g_lowhist[c * NLOW + t];   // one bin per thread
    chunk[t] = s;
    incl[t] = s;
    if (t == 0) tcnt = 0;
    __syncthreads();
#pragma unroll
    for (int off = 1; off < 256; off <<= 1) {
        unsigned v = (t >= off) ? incl[t - off] : 0u;
        __syncthreads();
        incl[t] += v;
        __syncthreads();
    }
    int excl = (int)incl[t] - (int)chunk[t];
    if ((int)incl[t] >= k && excl < k) {
        sh_thrbin = t;
        sh_kl2 = k - excl;
    }
    __syncthreads();
    int thrbin = sh_thrbin;
    int kl2 = sh_kl2;

    for (int j = t; j < m; j += 256) {
        int idx = lst[j];
        unsigned bits = g_keys[idx].x;
        int lb = (int)((bits >> 12) & 0xFFu);
        if (lb < thrbin) {
            int p = atomicAdd(&g_cnt[c], 1);
            g_list[(size_t)c * LCAP + p] = idx;
        } else if (lb == thrbin) {
            int p = atomicAdd(&tcnt, 1);
            if (p < TIECAP) { tkey[p] = bits; tidx[p] = idx; }
        }
    }
    __syncthreads();
    int tc = tcnt;
    if (tc <= TIECAP) {
        for (int j = t; j < tc; j += 256) {
            unsigned key = tkey[j];
            int idx = tidx[j];
            int rank = 0;
            for (int q = 0; q < tc; q++) {
                unsigned kq = tkey[q];
                rank += (kq < key) || (kq == key && tidx[q] < idx);
            }
            if (rank < kl2) {
                int p = atomicAdd(&g_cnt[c], 1);
                g_list[(size_t)c * LCAP + p] = idx;
            }
        }
    } else {
        // pathological: tie bin overflow -> rank against full candidate list
        for (int j = t; j < m; j += 256) {
            int idx = lst[j];
            unsigned key = g_keys[idx].x;
            if ((int)((key >> 12) & 0xFFu) != thrbin) continue;
            int rank = 0;
            for (int q = 0; q < m; q++) {
                int iq = lst[q];
                unsigned kq = g_keys[iq].x;
                if ((int)((kq >> 12) & 0xFFu) != thrbin) continue;
                rank += (kq < key) || (kq == key && iq < idx);
            }
            if (rank < kl2) {
                int p = atomicAdd(&g_cnt[c], 1);
                g_list[(size_t)c * LCAP + p] = idx;
            }
        }
    }
}

// ---- kernel 5: support sums -> REDG into g_Wc; last block -> norms -------
__global__ void k_sum(const float* __restrict__ supports,
                      const float* __restrict__ feat, int N) {
    int c = blockIdx.y;
    int blk = blockIdx.x;
    int cnt = g_cnt[c]; if (cnt > LCAP) cnt = LCAP;
    int w = threadIdx.x >> 5, lane = threadIdx.x & 31;
    int wg = blk * 8 + w;
    const int* lst = &g_list[(size_t)c * LCAP];

    float acc[16];
#pragma unroll
    for (int j = 0; j < 16; j++) acc[j] = 0.f;

    for (int idx = wg; idx < cnt; idx += CH2 * 8) {
        int r = lst[idx];
        const float4* p = (const float4*)((r < N) ? supports + (size_t)r * D
                                                  : feat + (size_t)(r - N) * D);
        float4 v[4];
        float ss = 0.f;
#pragma unroll
        for (int j = 0; j < 4; j++) {
            v[j] = p[lane + 32 * j];
            ss += v[j].x * v[j].x + v[j].y * v[j].y + v[j].z * v[j].z + v[j].w * v[j].w;
        }
#pragma unroll
        for (int o = 16; o; o >>= 1) ss += __shfl_xor_sync(0xffffffffu, ss, o);
        float rn = 1.f / fmaxf(sqrtf(ss), 1e-12f);
#pragma unroll
        for (int j = 0; j < 4; j++) {
            acc[4 * j + 0] += v[j].x * rn;
            acc[4 * j + 1] += v[j].y * rn;
            acc[4 * j + 2] += v[j].z * rn;
            acc[4 * j + 3] += v[j].w * rn;
        }
    }

    __shared__ float sacc[D];
    for (int d = threadIdx.x; d < D; d += blockDim.x) sacc[d] = 0.f;
    __syncthreads();
#pragma unroll
    for (int j = 0; j < 4; j++) {
        int d = 4 * (lane + 32 * j);
        atomicAdd(&sacc[d + 0], acc[4 * j + 0]);
        atomicAdd(&sacc[d + 1], acc[4 * j + 1]);
        atomicAdd(&sacc[d + 2], acc[4 * j + 2]);
        atomicAdd(&sacc[d + 3], acc[4 * j + 3]);
    }
    __syncthreads();
    for (int d = threadIdx.x; d < D; d += blockDim.x)
        atomicAdd(&g_Wc[c * D + d], sacc[d]);   // REDG, no return

    // all threads fence their REDGs, then one thread claims the done slot
    __syncthreads();
    __threadfence();
    __syncthreads();
    __shared__ int amlast;
    if (threadIdx.x == 0) {
        unsigned v = atomicAdd(&g_done, 1u);
        amlast = (v == (unsigned)(gridDim.x * gridDim.y - 1));
    }
    __syncthreads();
    if (!amlast) return;
    if (threadIdx.x == 0) g_done = 0u;
    for (int cc = w; cc < C; cc += 8) {
        float ss = 0.f;
#pragma unroll
        for (int j = 0; j < 16; j++) {
            float v = g_Wc[cc * D + lane + 32 * j];
            ss += v * v;
        }
#pragma unroll
        for (int o = 16; o; o >>= 1) ss += __shfl_xor_sync(0xffffffffu, ss, o);
        if (lane == 0)
            g_rn[cc] = 1.f / fmaxf(sqrtf(ss), 1e-12f);
    }
}

// ---- kernel 6: final GEMM out = feature @ (Wc*rn); re-zero histograms ----
__global__ void k_gemm2(const float* __restrict__ feat, float* __restrict__ out,
                        int B) {
    int tid = blockIdx.x * blockDim.x + threadIdx.x;
    int nth = gridDim.x * blockDim.x;
    // restore zero invariants for the next run (selB is done by now)
    for (int i = tid; i < C * NBA; i += nth) g_histA[i] = 0u;
    for (int i = tid; i < C * NLOW; i += nth) g_lowhist[i] = 0u;

    int warp = tid >> 5;
    int lane = threadIdx.x & 31;
    if (warp >= B) return;
    float rnl = (lane < C) ? g_rn[lane] : 0.f;
    const float4* f4 = (const float4*)(feat + (size_t)warp * D);
    const float4* w4 = (const float4*)g_Wc;
    float4 fv[4];
#pragma unroll
    for (int j = 0; j < 4; j++) fv[j] = f4[lane + 32 * j];
    float s[C];
#pragma unroll
    for (int c = 0; c < C; c++) s[c] = 0.f;
#pragma unroll
    for (int j = 0; j < 4; j++) {
        float4 fj = fv[j];
#pragma unroll
        for (int c = 0; c < C; c++) {
            float4 wv = w4[c * (D / 4) + lane + 32 * j];
            s[c] += fj.x * wv.x + fj.y * wv.y + fj.z * wv.z + fj.w * wv.w;
        }
    }
#pragma unroll
    for (int o = 16; o; o >>= 1) {
#pragma unroll
        for (int c = 0; c < C; c++)
            s[c] += __shfl_xor_sync(0xffffffffu, s[c], o);
    }
    float myv = 0.f;
#pragma unroll
    for (int c = 0; c < C; c++)
        if (lane == c) myv = s[c];
    if (lane < C) out[(size_t)warp * C + lane] = myv * rnl;
}

// ---- launch ---------------------------------------------------------------
extern "C" void kernel_launch(void* const* d_in, const int* in_sizes, int n_in,
                              void* d_out, int out_size) {
    const float* feature  = (const float*)d_in[0];
    const float* clf_w    = (const float*)d_in[1];
    const float* clf_b    = (const float*)d_in[2];
    const float* supports = (const float*)d_in[3];
    const float* ent_bank = (const float*)d_in[4];
    const int*   labels   = (const int*)d_in[5];
    const int*   kptr     = (const int*)d_in[6];

    int Cc = in_sizes[2];          // 17
    int Dv = in_sizes[1] / Cc;     // 512
    int B  = in_sizes[0] / Dv;     // 4096
    int N  = in_sizes[4];          // 100000
    int R  = N + B;
    (void)n_in; (void)out_size; (void)Dv;

    float* out = (float*)d_out;

    int blk1 = (B * 32 + 255) / 256;
    k_logits<<<blk1, 256>>>(feature, clf_w, clf_b, ent_bank, labels, B, N);
    k_scanA<<<C, 256>>>(kptr);
    k_compact<<<(R + 255) / 256, 256>>>(R);
    k_selB<<<C, 256>>>();
    dim3 g5(CH2, C);
    k_sum<<<g5, 256>>>(supports, feature, N);
    k_gemm2<<<blk1, 256>>>(feature, out, B);
}